// round 15
// baseline (speedup 1.0000x reference)
#include <cuda_runtime.h>
#include <cuda_bf16.h>
#include <cstdint>
#include <math.h>

#define NVV 778
#define NC   146      // 1 + 10 beta + 135 pose_feature
#define NCOL 784      // 768 joint cols + 15 finger cols + 1 pad
#define BMAX 4096
#define KP   448      // split-K: [Xh(146)|Xh(146)|Xl(146)|pad10]
#define NCHP 7        // vertex chunks for kC

// ---- scratch (static device globals; no allocation) ----
__device__ float g_S[256];
__device__ float g_JT[11 * 48];
__device__ float g_A[BMAX * 192];   // skinning transforms 16 x (R9 + t3)
__device__ float g_M[BMAX * NCOL];  // GEMM result (fp32)
__device__ __nv_bfloat16 g_Xb[BMAX * KP];   // split-bf16 X (k-permuted)
__device__ __nv_bfloat16 g_Ct[NCOL * KP];   // split-bf16 C^T (k-permuted)
__device__ float g_Cpart[NCHP][NC * NCOL];  // per-chunk partial C rows

__constant__ int c_par[16]   = {-1,0,1,2,0,4,5,0,7,8,0,10,11,0,13,14};
__constant__ int c_depth[16] = {0,1,2,3,1,2,3,1,2,3,1,2,3,1,2,3};
__constant__ int c_fidx[5]   = {734,333,443,555,678};

__device__ __forceinline__ uint32_t smem_u32(const void* p) {
    uint32_t a;
    asm("{ .reg .u64 t; cvta.to.shared.u64 t, %1; cvt.u32.u64 %0, t; }" : "=r"(a) : "l"(p));
    return a;
}

__device__ __forceinline__ void bf16_split(float v, __nv_bfloat16& hi, __nv_bfloat16& lo) {
    hi = __float2bfloat16(v);
    lo = __float2bfloat16(v - __bfloat162float(hi));
}

// k-permutation within each 16-block: pairs [p0,p4,p1,p5,p2,p6,p3,p7]
__device__ __forceinline__ int permk(int k) {
    int blk = k & ~15, kk = k & 15;
    int q = kk >> 1, r = kk & 1;
    int slot = (q < 4) ? (q << 1) : (((q - 4) << 1) + 1);
    return blk + (slot << 1) + r;
}

// ============================================================
// kC (chunked, C partials only): grid (146, 7).
// ============================================================
#define CHV 112
__global__ void __launch_bounds__(256) kC(
        const float* __restrict__ vt, const float* __restrict__ sd,
        const float* __restrict__ pd, const float* __restrict__ Jreg,
        const float* __restrict__ Wt) {
    __shared__ float Ds[CHV * 3];
    __shared__ float Jr[CHV * 16];
    __shared__ float Wc[CHV * 16];
    int r = blockIdx.x, ch = blockIdx.y, t = threadIdx.x;
    int v0 = ch * CHV;
    int n = NVV - v0; if (n > CHV) n = CHV;
    const float* src = (r == 0) ? vt : (r < 11 ? sd + (r - 1) * (NVV * 3)
                                               : pd + (r - 11) * (NVV * 3));
    for (int i = t; i < n * 3; i += 256) Ds[i] = src[v0 * 3 + i];
    for (int i = t; i < n * 16; i += 256) {
        Jr[i] = Jreg[v0 * 16 + i];
        Wc[i] = Wt[v0 * 16 + i];
    }
    __syncthreads();

    int k = t >> 4, j = t & 15;
    float a0 = 0.f, a1 = 0.f, a2 = 0.f;
    #pragma unroll 4
    for (int v = 0; v < n; ++v) {
        float e = Jr[v * 16 + k] * Wc[v * 16 + j];
        a0 += e * Ds[v * 3 + 0];
        a1 += e * Ds[v * 3 + 1];
        a2 += e * Ds[v * 3 + 2];
    }
    float* out = g_Cpart[ch] + (size_t)r * NCOL;
    out[t * 3 + 0] = a0;
    out[t * 3 + 1] = a1;
    out[t * 3 + 2] = a2;
    if (t < 15) {
        int fv = c_fidx[t / 3];
        float fvv = 0.f;
        if (fv >= v0 && fv < v0 + n) fvv = Ds[(fv - v0) * 3 + (t % 3)];
        out[768 + t] = fvv;
    }
    if (t == 15) out[783] = 0.f;
}

// ============================================================
// kCtC: reduce 7 C partials -> split-bf16 g_Ct (k-permuted).
// ============================================================
__global__ void __launch_bounds__(256) kCtC() {
    int idx = blockIdx.x * 256 + threadIdx.x;
    if (idx >= NC * NCOL) return;
    int r = idx / NCOL, nn = idx - r * NCOL;
    float s = 0.f;
    #pragma unroll
    for (int ch = 0; ch < NCHP; ++ch) s += g_Cpart[ch][(size_t)r * NCOL + nn];
    __nv_bfloat16 hi, lo;
    bf16_split(s, hi, lo);
    __nv_bfloat16* row = g_Ct + (size_t)nn * KP;
    row[permk(r)] = hi;
    row[permk(146 + r)] = lo;
    row[permk(292 + r)] = hi;
    if (r == 0) {
        __nv_bfloat16 z = __float2bfloat16(0.f);
        #pragma unroll
        for (int l = 438; l < KP; ++l) row[permk(l)] = z;
    }
}

// ============================================================
// kJTS: independent of kC.  blocks 0..10: JT row r (48 vals);
// block 11: S (256 vals).  Staged smem chunks, coalesced reads.
// ============================================================
__global__ void __launch_bounds__(256) kJTS(
        const float* __restrict__ vt, const float* __restrict__ sd,
        const float* __restrict__ Jreg, const float* __restrict__ Wt) {
    __shared__ float Ds[CHV * 3];
    __shared__ float Jr[CHV * 16];
    __shared__ float Wc[CHV * 16];
    int r = blockIdx.x, t = threadIdx.x;
    if (r < 11) {
        const float* src = (r == 0) ? vt : sd + (r - 1) * (NVV * 3);
        float jt = 0.f;
        int jj = t / 3, cc = t - jj * 3;
        for (int v0 = 0; v0 < NVV; v0 += CHV) {
            int n = NVV - v0; if (n > CHV) n = CHV;
            __syncthreads();
            for (int i = t; i < n * 3; i += 256) Ds[i] = src[v0 * 3 + i];
            for (int i = t; i < n * 16; i += 256) Jr[i] = Jreg[v0 * 16 + i];
            __syncthreads();
            if (t < 48) {
                #pragma unroll 4
                for (int v = 0; v < n; ++v) jt += Jr[v * 16 + jj] * Ds[v * 3 + cc];
            }
        }
        if (t < 48) g_JT[r * 48 + t] = jt;
    } else {
        int k = t >> 4, j = t & 15;
        float ss = 0.f;
        for (int v0 = 0; v0 < NVV; v0 += CHV) {
            int n = NVV - v0; if (n > CHV) n = CHV;
            __syncthreads();
            for (int i = t; i < n * 16; i += 256) {
                Jr[i] = Jreg[v0 * 16 + i];
                Wc[i] = Wt[v0 * 16 + i];
            }
            __syncthreads();
            #pragma unroll 4
            for (int v = 0; v < n; ++v) ss += Jr[v * 16 + k] * Wc[v * 16 + j];
        }
        g_S[t] = ss;
    }
}

// ============================================================
// kBatch: per-batch kinematics; emits k-permuted split-bf16 Xb.
// ============================================================
__global__ void kBatch(const float* __restrict__ beta, const float* __restrict__ theta,
                       const float* __restrict__ hm, const float* __restrict__ hc, int B) {
    __shared__ float hcs[45 * 45];
    __shared__ float hms[45];
    __shared__ float JTs[11 * 48];
    __shared__ float wsPose[8][48];
    __shared__ float wsA[8][16 * 12];
    __shared__ float wsJ[8][48];
    __shared__ float wsBeta[8][10];
    __shared__ float wsX[8][146];

    int tid = threadIdx.x, warp = tid >> 5, lane = tid & 31;
    for (int i = tid; i < 2025; i += 256) hcs[i] = hc[i];
    if (tid < 45) hms[tid] = hm[tid];
    for (int i = tid; i < 528; i += 256) JTs[i] = g_JT[i];
    __syncthreads();

    int b = blockIdx.x * 8 + warp;
    if (b >= B) return;

    float* P = wsPose[warp];
    const float* th = theta + b * 48;
    if (lane < 16) { P[lane] = th[lane]; P[lane + 16] = th[lane + 16]; P[lane + 32] = th[lane + 32]; }
    if (lane < 10) wsBeta[warp][lane] = beta[b * 10 + lane];
    __syncwarp();

    int i0 = lane, i1 = lane + 32;
    float acc0 = hms[i0];
    float acc1 = (i1 < 45) ? hms[i1] : 0.f;
    #pragma unroll 5
    for (int p = 0; p < 45; ++p) {
        float tv = P[3 + p];
        acc0 += tv * hcs[p * 45 + i0];
        if (i1 < 45) acc1 += tv * hcs[p * 45 + i1];
    }
    __syncwarp();
    P[3 + i0] = acc0;
    if (i1 < 45) P[3 + i1] = acc1;
    __syncwarp();

    float* xs = wsX[warp];
    float R[9];
    if (lane < 16) {
        float rx = P[3 * lane], ry = P[3 * lane + 1], rz = P[3 * lane + 2];
        float ex = rx + 1e-8f, ey = ry + 1e-8f, ez = rz + 1e-8f;
        float ang = sqrtf(ex * ex + ey * ey + ez * ez);
        float inv = 1.0f / ang;
        float ax = rx * inv, ay = ry * inv, az = rz * inv;
        float s, co;
        sincosf(ang, &s, &co);
        float t1 = 1.0f - co;
        R[0] = 1.0f - t1 * (ay * ay + az * az);
        R[1] = -s * az + t1 * ax * ay;
        R[2] =  s * ay + t1 * ax * az;
        R[3] =  s * az + t1 * ax * ay;
        R[4] = 1.0f - t1 * (ax * ax + az * az);
        R[5] = -s * ax + t1 * ay * az;
        R[6] = -s * ay + t1 * ax * az;
        R[7] =  s * ax + t1 * ay * az;
        R[8] = 1.0f - t1 * (ax * ax + ay * ay);
        if (lane >= 1) {
            #pragma unroll
            for (int e = 0; e < 9; ++e)
                xs[11 + (lane - 1) * 9 + e] = R[e] - ((e == 0 || e == 4 || e == 8) ? 1.0f : 0.0f);
        }
    }
    if (lane == 0) xs[0] = 1.0f;
    if (lane < 10) xs[1 + lane] = wsBeta[warp][lane];
    __syncwarp();

    {
        __nv_bfloat16* xb = g_Xb + (size_t)b * KP;
        for (int l = lane; l < KP; l += 32) {
            __nv_bfloat16 o;
            if (l < 146) o = __float2bfloat16(xs[l]);
            else if (l < 292) o = __float2bfloat16(xs[l - 146]);
            else if (l < 438) {
                float v = xs[l - 292];
                __nv_bfloat16 h = __float2bfloat16(v);
                o = __float2bfloat16(v - __bfloat162float(h));
            } else o = __float2bfloat16(0.f);
            xb[permk(l)] = o;
        }
    }

    float* Jv = wsJ[warp];
    for (int o = lane; o < 48; o += 32) {
        float acc = JTs[o];
        #pragma unroll
        for (int s2 = 0; s2 < 10; ++s2) acc += wsBeta[warp][s2] * JTs[(s2 + 1) * 48 + o];
        Jv[o] = acc;
    }
    __syncwarp();

    float AR[9], At[3];
    float tl0 = 0.f, tl1 = 0.f, tl2 = 0.f;
    if (lane < 16) {
        int par = c_par[lane];
        if (lane == 0) { tl0 = Jv[0]; tl1 = Jv[1]; tl2 = Jv[2]; }
        else {
            tl0 = Jv[3 * lane + 0] - Jv[3 * par + 0];
            tl1 = Jv[3 * lane + 1] - Jv[3 * par + 1];
            tl2 = Jv[3 * lane + 2] - Jv[3 * par + 2];
        }
    }
    float* Aw = wsA[warp];
    if (lane == 0) {
        #pragma unroll
        for (int e = 0; e < 9; ++e) { AR[e] = R[e]; Aw[e] = R[e]; }
        At[0] = tl0; At[1] = tl1; At[2] = tl2;
        Aw[9] = tl0; Aw[10] = tl1; Aw[11] = tl2;
    }
    __syncwarp();
    for (int level = 1; level <= 3; ++level) {
        if (lane < 16 && c_depth[lane] == level) {
            int par = c_par[lane];
            float Pp[12];
            #pragma unroll
            for (int e = 0; e < 12; ++e) Pp[e] = Aw[par * 12 + e];
            #pragma unroll
            for (int rr = 0; rr < 3; ++rr)
                #pragma unroll
                for (int ccx = 0; ccx < 3; ++ccx)
                    AR[rr * 3 + ccx] = Pp[rr * 3 + 0] * R[0 + ccx] +
                                       Pp[rr * 3 + 1] * R[3 + ccx] +
                                       Pp[rr * 3 + 2] * R[6 + ccx];
            At[0] = Pp[0] * tl0 + Pp[1] * tl1 + Pp[2] * tl2 + Pp[9];
            At[1] = Pp[3] * tl0 + Pp[4] * tl1 + Pp[5] * tl2 + Pp[10];
            At[2] = Pp[6] * tl0 + Pp[7] * tl1 + Pp[8] * tl2 + Pp[11];
            #pragma unroll
            for (int e = 0; e < 9; ++e) Aw[lane * 12 + e] = AR[e];
            Aw[lane * 12 + 9] = At[0]; Aw[lane * 12 + 10] = At[1]; Aw[lane * 12 + 11] = At[2];
        }
        __syncwarp();
    }
    if (lane < 16) {
        float jx = Jv[3 * lane], jy = Jv[3 * lane + 1], jz = Jv[3 * lane + 2];
        At[0] -= AR[0] * jx + AR[1] * jy + AR[2] * jz;
        At[1] -= AR[3] * jx + AR[4] * jy + AR[5] * jz;
        At[2] -= AR[6] * jx + AR[7] * jy + AR[8] * jz;
        float* ap = g_A + b * 192 + lane * 12;
        #pragma unroll
        for (int e = 0; e < 9; ++e) ap[e] = AR[e];
        ap[9] = At[0]; ap[10] = At[1]; ap[11] = At[2];
    }
}

// ============================================================
// kGemmW: pipelined mma.sync bf16 GEMM (R14 measured-good).
// ============================================================
#define MT 64
#define NT 112
#define KC 64
#define KCPAD 72
#define A_H (MT * KCPAD)
#define B_H (NT * KCPAD)
#define STG_H (A_H + B_H)
#define NSTAGE 3
#define NCHUNK 7
#define SM_TOTAL (NSTAGE * STG_H * 2)   // 76,032 bytes

__device__ __forceinline__ void mma16816(float* c, const uint32_t* a, const uint32_t* b) {
    asm volatile(
        "mma.sync.aligned.m16n8k16.row.col.f32.bf16.bf16.f32 "
        "{%0,%1,%2,%3}, {%4,%5,%6,%7}, {%8,%9}, {%0,%1,%2,%3};"
        : "+f"(c[0]), "+f"(c[1]), "+f"(c[2]), "+f"(c[3])
        : "r"(a[0]), "r"(a[1]), "r"(a[2]), "r"(a[3]), "r"(b[0]), "r"(b[1]));
}

__global__ void __launch_bounds__(256, 3) kGemmW(int B) {
    extern __shared__ __nv_bfloat16 sm[];
    int tid = threadIdx.x, wid = tid >> 5, lane = tid & 31;
    int b0 = blockIdx.x * MT, n0 = blockIdx.y * NT;
    uint32_t sbase = smem_u32(sm);

    auto issue = [&](int c) {
        int s = c % NSTAGE;
        uint32_t abase = sbase + (uint32_t)(s * STG_H) * 2;
        uint32_t bbase = abase + A_H * 2;
        const char* ga = (const char*)g_Xb + (size_t)b0 * (KP * 2) + c * (KC * 2);
        #pragma unroll 1
        for (int i = tid; i < MT * 8; i += 256) {
            int row = i >> 3, cc = i & 7;
            uint32_t dst = abase + (uint32_t)(row * KCPAD + cc * 8) * 2;
            const char* src = ga + (size_t)row * (KP * 2) + cc * 16;
            asm volatile("cp.async.ca.shared.global [%0], [%1], 16;" :: "r"(dst), "l"(src));
        }
        const char* gb = (const char*)g_Ct + (size_t)n0 * (KP * 2) + c * (KC * 2);
        #pragma unroll 1
        for (int i = tid; i < NT * 8; i += 256) {
            int row = i >> 3, cc = i & 7;
            uint32_t dst = bbase + (uint32_t)(row * KCPAD + cc * 8) * 2;
            const char* src = gb + (size_t)row * (KP * 2) + cc * 16;
            asm volatile("cp.async.ca.shared.global [%0], [%1], 16;" :: "r"(dst), "l"(src));
        }
        asm volatile("cp.async.commit_group;");
    };

    int wm = (wid & 3) * 16;
    int wn = (wid >> 2) * 56;
    int qr = lane >> 2, qc = lane & 3;

    float acc[7][4];
    #pragma unroll
    for (int tn = 0; tn < 7; ++tn)
        #pragma unroll
        for (int e = 0; e < 4; ++e) acc[tn][e] = 0.f;

    issue(0); issue(1);

    for (int c = 0; c < NCHUNK; ++c) {
        if (c < NCHUNK - 1) { asm volatile("cp.async.wait_group 1;"); }
        else { asm volatile("cp.async.wait_group 0;"); }
        __syncthreads();
        if (c + 2 < NCHUNK) issue(c + 2);

        const __nv_bfloat16* As = sm + (c % NSTAGE) * STG_H;
        const __nv_bfloat16* Bs = As + A_H;
        #pragma unroll
        for (int k0 = 0; k0 < KC; k0 += 16) {
            uint32_t bf[7][2];
            #pragma unroll
            for (int tn = 0; tn < 7; ++tn) {
                uint2 bv = *(const uint2*)(Bs + (wn + tn * 8 + qr) * KCPAD + k0 + 4 * qc);
                bf[tn][0] = bv.x; bf[tn][1] = bv.y;
            }
            uint32_t af[4];
            {
                uint2 av0 = *(const uint2*)(As + (wm + qr) * KCPAD + k0 + 4 * qc);
                uint2 av1 = *(const uint2*)(As + (wm + qr + 8) * KCPAD + k0 + 4 * qc);
                af[0] = av0.x; af[2] = av0.y;
                af[1] = av1.x; af[3] = av1.y;
            }
            #pragma unroll
            for (int tn = 0; tn < 7; ++tn)
                mma16816(acc[tn], af, bf[tn]);
        }
    }

    __syncthreads();
    int row = b0 + wm + qr;
    #pragma unroll
    for (int tn = 0; tn < 7; ++tn) {
        int col = n0 + wn + tn * 8 + qc * 2;
        if (row < B)
            *(float2*)&g_M[(size_t)row * NCOL + col] = make_float2(acc[tn][0], acc[tn][1]);
        if (row + 8 < B)
            *(float2*)&g_M[(size_t)(row + 8) * NCOL + col] = make_float2(acc[tn][2], acc[tn][3]);
    }
}

// ============================================================
// kOut (measured-good): one warp per item, float4 staging.
// ============================================================
__global__ void kOut(const float* __restrict__ Wt, float* __restrict__ out, int B) {
    __shared__ float Ssm[256];
    __shared__ float Ms[8][784];
    __shared__ float As[8][192];
    int tid = threadIdx.x, warp = tid >> 5, lane = tid & 31;
    Ssm[tid] = g_S[tid];
    __syncthreads();
    int b = blockIdx.x * 8 + warp;
    if (b >= B) return;
    {
        const float4* mp = (const float4*)(g_M + (size_t)b * 784);
        float4* md = (float4*)Ms[warp];
        for (int i = lane; i < 196; i += 32) md[i] = mp[i];
        const float4* ap = (const float4*)(g_A + (size_t)b * 192);
        float4* ad = (float4*)As[warp];
        for (int i = lane; i < 48; i += 32) ad[i] = ap[i];
    }
    __syncwarp();
    if (lane < 21) {
        float a0 = 0.f, a1 = 0.f, a2 = 0.f;
        if (lane < 16) {
            int k = lane;
            #pragma unroll
            for (int j = 0; j < 16; ++j) {
                const float* Aj = &As[warp][j * 12];
                float s = Ssm[k * 16 + j];
                int base = (k * 16 + j) * 3;
                float m0 = Ms[warp][base], m1 = Ms[warp][base + 1], m2 = Ms[warp][base + 2];
                a0 += Aj[0] * m0 + Aj[1] * m1 + Aj[2] * m2 + Aj[9]  * s;
                a1 += Aj[3] * m0 + Aj[4] * m1 + Aj[5] * m2 + Aj[10] * s;
                a2 += Aj[6] * m0 + Aj[7] * m1 + Aj[8] * m2 + Aj[11] * s;
            }
        } else {
            int f = lane - 16;
            float v0 = Ms[warp][768 + f * 3], v1 = Ms[warp][768 + f * 3 + 1], v2 = Ms[warp][768 + f * 3 + 2];
            const float* wr = Wt + c_fidx[f] * 16;
            #pragma unroll
            for (int j = 0; j < 16; ++j) {
                const float* Aj = &As[warp][j * 12];
                float w = wr[j];
                a0 += w * (Aj[0] * v0 + Aj[1] * v1 + Aj[2] * v2 + Aj[9]);
                a1 += w * (Aj[3] * v0 + Aj[4] * v1 + Aj[5] * v2 + Aj[10]);
                a2 += w * (Aj[6] * v0 + Aj[7] * v1 + Aj[8] * v2 + Aj[11]);
            }
        }
        float* op = out + b * 63 + lane * 3;
        op[0] = a0; op[1] = a1; op[2] = a2;
    }
}

// ============================================================
extern "C" void kernel_launch(void* const* d_in, const int* in_sizes, int n_in,
                              void* d_out, int out_size) {
    const float* beta  = (const float*)d_in[0];
    const float* theta = (const float*)d_in[1];
    const float* vt    = (const float*)d_in[2];
    const float* sd    = (const float*)d_in[3];
    const float* pd    = (const float*)d_in[4];
    const float* Jreg  = (const float*)d_in[5];
    const float* W     = (const float*)d_in[6];
    const float* hm    = (const float*)d_in[7];
    const float* hc    = (const float*)d_in[8];
    int B = in_sizes[0] / 10;
    if (B > BMAX) B = BMAX;

    // streams/events created once, on the (uncaptured) first call.
    static cudaStream_t s1 = [] { cudaStream_t s;
        cudaStreamCreateWithFlags(&s, cudaStreamNonBlocking); return s; }();
    static cudaEvent_t eFork = [] { cudaEvent_t e;
        cudaEventCreateWithFlags(&e, cudaEventDisableTiming); return e; }();
    static cudaEvent_t eJoin = [] { cudaEvent_t e;
        cudaEventCreateWithFlags(&e, cudaEventDisableTiming); return e; }();
    static bool attrSet = [] {
        cudaFuncSetAttribute(kGemmW, cudaFuncAttributeMaxDynamicSharedMemorySize, SM_TOTAL);
        return true; }();
    (void)attrSet;

    // fork
    cudaEventRecord(eFork, 0);
    cudaStreamWaitEvent(s1, eFork, 0);

    // branch 0 (capture stream): C basis
    kC<<<dim3(NC, NCHP), 256>>>(vt, sd, pd, Jreg, W);
    kCtC<<<448, 256>>>();

    // branch 1 (side stream): kinematics
    kJTS<<<12, 256, 0, s1>>>(vt, sd, Jreg, W);
    kBatch<<<(B + 7) / 8, 256, 0, s1>>>(beta, theta, hm, hc, B);

    // join
    cudaEventRecord(eJoin, s1);
    cudaStreamWaitEvent(0, eJoin, 0);

    kGemmW<<<dim3((B + MT - 1) / MT, NCOL / NT), 256, SM_TOTAL>>>(B);
    kOut<<<(B + 7) / 8, 256>>>(W, (float*)d_out, B);
}

// round 16
// speedup vs baseline: 1.1829x; 1.1829x over previous
#include <cuda_runtime.h>
#include <cuda_bf16.h>
#include <cstdint>
#include <math.h>

#define NVV 778
#define NC   146      // 1 + 10 beta + 135 pose_feature
#define NCOL 784      // 768 joint cols + 15 finger cols + 1 pad
#define BMAX 4096
#define KP   448      // split-K: [Xh(146)|Xh(146)|Xl(146)|pad10]
#define NCHP 7        // vertex chunks for kC

// ---- scratch (static device globals; no allocation) ----
__device__ float g_S[256];
__device__ float g_A[BMAX * 192];   // skinning transforms 16 x (R9 + t3)
__device__ float g_M[BMAX * NCOL];  // GEMM result (fp32)
__device__ __nv_bfloat16 g_Xb[BMAX * KP];   // split-bf16 X (k-permuted)
__device__ __nv_bfloat16 g_Ct[NCOL * KP];   // split-bf16 C^T (k-permuted)
__device__ float g_Cpart[NCHP][NC * NCOL];  // per-chunk partial C rows
__device__ float g_Spart[NCHP][256];
__device__ float g_JTpart[NCHP][11 * 48];

__constant__ int c_fidx[5]   = {734,333,443,555,678};
// ancestor-at-depth-s for each joint (identity-pad = -1)
__constant__ int c_anc1[16] = { -1, 1, 1, 1, 4, 4, 4, 7, 7, 7,10,10,10,13,13,13};
__constant__ int c_anc2[16] = { -1,-1, 2, 2,-1, 5, 5,-1, 8, 8,-1,11,11,-1,14,14};
__constant__ int c_anc3[16] = { -1,-1,-1, 3,-1,-1, 6,-1,-1, 9,-1,-1,12,-1,-1,15};

__device__ __forceinline__ uint32_t smem_u32(const void* p) {
    uint32_t a;
    asm("{ .reg .u64 t; cvta.to.shared.u64 t, %1; cvt.u32.u64 %0, t; }" : "=r"(a) : "l"(p));
    return a;
}

__device__ __forceinline__ void bf16_split(float v, __nv_bfloat16& hi, __nv_bfloat16& lo) {
    hi = __float2bfloat16(v);
    lo = __float2bfloat16(v - __bfloat162float(hi));
}

// k-permutation within each 16-block: pairs [p0,p4,p1,p5,p2,p6,p3,p7]
__device__ __forceinline__ int permk(int k) {
    int blk = k & ~15, kk = k & 15;
    int q = kk >> 1, r = kk & 1;
    int slot = (q < 4) ? (q << 1) : (((q - 4) << 1) + 1);
    return blk + (slot << 1) + r;
}

// ============================================================
// kC (chunked): grid (146, 7) — known-good since R11.
// ============================================================
#define CHV 112
__global__ void __launch_bounds__(256) kC(
        const float* __restrict__ vt, const float* __restrict__ sd,
        const float* __restrict__ pd, const float* __restrict__ Jreg,
        const float* __restrict__ Wt) {
    __shared__ float Ds[CHV * 3];
    __shared__ float Jr[CHV * 16];
    __shared__ float Wc[CHV * 16];
    int r = blockIdx.x, ch = blockIdx.y, t = threadIdx.x;
    int v0 = ch * CHV;
    int n = NVV - v0; if (n > CHV) n = CHV;
    const float* src = (r == 0) ? vt : (r < 11 ? sd + (r - 1) * (NVV * 3)
                                               : pd + (r - 11) * (NVV * 3));
    for (int i = t; i < n * 3; i += 256) Ds[i] = src[v0 * 3 + i];
    for (int i = t; i < n * 16; i += 256) {
        Jr[i] = Jreg[v0 * 16 + i];
        Wc[i] = Wt[v0 * 16 + i];
    }
    __syncthreads();

    int k = t >> 4, j = t & 15;
    float a0 = 0.f, a1 = 0.f, a2 = 0.f, ss = 0.f;
    #pragma unroll 4
    for (int v = 0; v < n; ++v) {
        float e = Jr[v * 16 + k] * Wc[v * 16 + j];
        ss += e;
        a0 += e * Ds[v * 3 + 0];
        a1 += e * Ds[v * 3 + 1];
        a2 += e * Ds[v * 3 + 2];
    }
    float* out = g_Cpart[ch] + (size_t)r * NCOL;
    out[t * 3 + 0] = a0;
    out[t * 3 + 1] = a1;
    out[t * 3 + 2] = a2;
    if (t < 15) {
        int fv = c_fidx[t / 3];
        float fvv = 0.f;
        if (fv >= v0 && fv < v0 + n) fvv = Ds[(fv - v0) * 3 + (t % 3)];
        out[768 + t] = fvv;
    }
    if (t == 15) out[783] = 0.f;
    if (r == 0) g_Spart[ch][t] = ss;
    if (r < 11 && t < 48) {
        int jj = t / 3, cc = t - jj * 3;
        float jt = 0.f;
        #pragma unroll 4
        for (int v = 0; v < n; ++v) jt += Jr[v * 16 + jj] * Ds[v * 3 + cc];
        g_JTpart[ch][r * 48 + t] = jt;
    }
}

// ============================================================
// kCtBatch: one launch.  Batch blocks FIRST (long pole), then
// 448 C-reduce blocks.
// ============================================================
__global__ void __launch_bounds__(256) kCtBatch(
        const float* __restrict__ beta, const float* __restrict__ theta,
        const float* __restrict__ hm, const float* __restrict__ hc, int B, int nB) {
    int tid = threadIdx.x;
    if ((int)blockIdx.x >= nB) {
        // ---- C reduce part ----
        int idx = (blockIdx.x - nB) * 256 + tid;
        if (idx >= NC * NCOL) return;
        int r = idx / NCOL, nn = idx - r * NCOL;
        float s = 0.f;
        #pragma unroll
        for (int ch = 0; ch < NCHP; ++ch) s += g_Cpart[ch][(size_t)r * NCOL + nn];
        __nv_bfloat16 hi, lo;
        bf16_split(s, hi, lo);
        __nv_bfloat16* row = g_Ct + (size_t)nn * KP;
        row[permk(r)] = hi;
        row[permk(146 + r)] = lo;
        row[permk(292 + r)] = hi;
        if (r == 0) {
            __nv_bfloat16 z = __float2bfloat16(0.f);
            #pragma unroll
            for (int l = 438; l < KP; ++l) row[permk(l)] = z;
        }
        return;
    }

    // ---- batch part ----
    __shared__ float hcs[45 * 45];
    __shared__ float hms[45];
    __shared__ float JTs[11 * 48];
    __shared__ float wsPose[8][48];
    __shared__ float wsJ[8][48];
    __shared__ float wsBeta[8][10];
    __shared__ float wsX[8][146];

    int warp = tid >> 5, lane = tid & 31;
    for (int i = tid; i < 2025; i += 256) hcs[i] = hc[i];
    if (tid < 45) hms[tid] = hm[tid];
    for (int i = tid; i < 528; i += 256) {
        float s = 0.f;
        #pragma unroll
        for (int ch = 0; ch < NCHP; ++ch) s += g_JTpart[ch][i];
        JTs[i] = s;
    }
    int bb = blockIdx.x;
    if (bb == 0) {
        float s = 0.f;
        #pragma unroll
        for (int ch = 0; ch < NCHP; ++ch) s += g_Spart[ch][tid];
        g_S[tid] = s;
    }
    __syncthreads();

    int b = bb * 8 + warp;
    if (b >= B) return;

    float* P = wsPose[warp];
    const float* th = theta + b * 48;
    if (lane < 16) { P[lane] = th[lane]; P[lane + 16] = th[lane + 16]; P[lane + 32] = th[lane + 32]; }
    if (lane < 10) wsBeta[warp][lane] = beta[b * 10 + lane];
    __syncwarp();

    int i0 = lane, i1 = lane + 32;
    float acc0 = hms[i0];
    float acc1 = (i1 < 45) ? hms[i1] : 0.f;
    #pragma unroll 5
    for (int p = 0; p < 45; ++p) {
        float tv = P[3 + p];
        acc0 += tv * hcs[p * 45 + i0];
        if (i1 < 45) acc1 += tv * hcs[p * 45 + i1];
    }
    __syncwarp();
    P[3 + i0] = acc0;
    if (i1 < 45) P[3 + i1] = acc1;
    __syncwarp();

    float* xs = wsX[warp];
    float R[9] = {1.f, 0.f, 0.f, 0.f, 1.f, 0.f, 0.f, 0.f, 1.f};
    float tl0 = 0.f, tl1 = 0.f, tl2 = 0.f;
    if (lane < 16) {
        float rx = P[3 * lane], ry = P[3 * lane + 1], rz = P[3 * lane + 2];
        float ex = rx + 1e-8f, ey = ry + 1e-8f, ez = rz + 1e-8f;
        float ang = sqrtf(ex * ex + ey * ey + ez * ez);
        float inv = 1.0f / ang;
        float ax = rx * inv, ay = ry * inv, az = rz * inv;
        float s, co;
        __sincosf(ang, &s, &co);
        float t1 = 1.0f - co;
        R[0] = 1.0f - t1 * (ay * ay + az * az);
        R[1] = -s * az + t1 * ax * ay;
        R[2] =  s * ay + t1 * ax * az;
        R[3] =  s * az + t1 * ax * ay;
        R[4] = 1.0f - t1 * (ax * ax + az * az);
        R[5] = -s * ax + t1 * ay * az;
        R[6] = -s * ay + t1 * ax * az;
        R[7] =  s * ax + t1 * ay * az;
        R[8] = 1.0f - t1 * (ax * ax + ay * ay);
        if (lane >= 1) {
            #pragma unroll
            for (int e = 0; e < 9; ++e)
                xs[11 + (lane - 1) * 9 + e] = R[e] - ((e == 0 || e == 4 || e == 8) ? 1.0f : 0.0f);
        }
    }
    if (lane == 0) xs[0] = 1.0f;
    if (lane < 10) xs[1 + lane] = wsBeta[warp][lane];
    __syncwarp();

    // k-permuted split-bf16 Xb row
    {
        __nv_bfloat16* xb = g_Xb + (size_t)b * KP;
        for (int l = lane; l < KP; l += 32) {
            __nv_bfloat16 o;
            if (l < 146) o = __float2bfloat16(xs[l]);
            else if (l < 292) o = __float2bfloat16(xs[l - 146]);
            else if (l < 438) {
                float v = xs[l - 292];
                __nv_bfloat16 h = __float2bfloat16(v);
                o = __float2bfloat16(v - __bfloat162float(h));
            } else o = __float2bfloat16(0.f);
            xb[permk(l)] = o;
        }
    }

    float* Jv = wsJ[warp];
    for (int o = lane; o < 48; o += 32) {
        float acc = JTs[o];
        #pragma unroll
        for (int s2 = 0; s2 < 10; ++s2) acc += wsBeta[warp][s2] * JTs[(s2 + 1) * 48 + o];
        Jv[o] = acc;
    }
    __syncwarp();

    // local bone translation per lane
    {
        int li = (lane < 16) ? lane : 0;
        int par = 0;
        // parent table inline (root handled below)
        const int parArr = 0; (void)parArr;
        if (li == 0) { tl0 = Jv[0]; tl1 = Jv[1]; tl2 = Jv[2]; }
        else {
            int p = (li == 1 || li == 4 || li == 7 || li == 10 || li == 13) ? 0
                  : li - 1;
            par = p;
            tl0 = Jv[3 * li + 0] - Jv[3 * par + 0];
            tl1 = Jv[3 * li + 1] - Jv[3 * par + 1];
            tl2 = Jv[3 * li + 2] - Jv[3 * par + 2];
        }
    }

    // ---- shuffle-parallel kinematic chain: each lane walks its path ----
    int li = (lane < 16) ? lane : 0;
    float M[9], Tt[3];
    #pragma unroll
    for (int e = 0; e < 9; ++e) M[e] = __shfl_sync(0xFFFFFFFF, R[e], 0);
    Tt[0] = __shfl_sync(0xFFFFFFFF, tl0, 0);
    Tt[1] = __shfl_sync(0xFFFFFFFF, tl1, 0);
    Tt[2] = __shfl_sync(0xFFFFFFFF, tl2, 0);
    if (li == 0) {               // root: M=R0, T=tl0 already (lane 0 values)
        // nothing more
    }
    const int* ancs[3] = {c_anc1, c_anc2, c_anc3};
    #pragma unroll
    for (int s = 0; s < 3; ++s) {
        int vs = ancs[s][li];
        int srcl = (vs >= 0) ? vs : 0;
        float Rs[9], ts0, ts1, ts2;
        #pragma unroll
        for (int e = 0; e < 9; ++e) Rs[e] = __shfl_sync(0xFFFFFFFF, R[e], srcl);
        ts0 = __shfl_sync(0xFFFFFFFF, tl0, srcl);
        ts1 = __shfl_sync(0xFFFFFFFF, tl1, srcl);
        ts2 = __shfl_sync(0xFFFFFFFF, tl2, srcl);
        if (vs >= 0) {
            // T = M*ts + T ; M = M*Rs
            float n0 = M[0] * ts0 + M[1] * ts1 + M[2] * ts2 + Tt[0];
            float n1 = M[3] * ts0 + M[4] * ts1 + M[5] * ts2 + Tt[1];
            float n2 = M[6] * ts0 + M[7] * ts1 + M[8] * ts2 + Tt[2];
            Tt[0] = n0; Tt[1] = n1; Tt[2] = n2;
            float NM[9];
            #pragma unroll
            for (int rr = 0; rr < 3; ++rr)
                #pragma unroll
                for (int cc = 0; cc < 3; ++cc)
                    NM[rr * 3 + cc] = M[rr * 3 + 0] * Rs[0 + cc] +
                                      M[rr * 3 + 1] * Rs[3 + cc] +
                                      M[rr * 3 + 2] * Rs[6 + cc];
            #pragma unroll
            for (int e = 0; e < 9; ++e) M[e] = NM[e];
        }
    }

    if (lane < 16) {
        float jx = Jv[3 * lane], jy = Jv[3 * lane + 1], jz = Jv[3 * lane + 2];
        Tt[0] -= M[0] * jx + M[1] * jy + M[2] * jz;
        Tt[1] -= M[3] * jx + M[4] * jy + M[5] * jz;
        Tt[2] -= M[6] * jx + M[7] * jy + M[8] * jz;
        float* ap = g_A + b * 192 + lane * 12;
        #pragma unroll
        for (int e = 0; e < 9; ++e) ap[e] = M[e];
        ap[9] = Tt[0]; ap[10] = Tt[1]; ap[11] = Tt[2];
    }
}

// ============================================================
// kGemmW: pipelined mma.sync bf16 GEMM (R14 measured-good).
// ============================================================
#define MT 64
#define NT 112
#define KC 64
#define KCPAD 72
#define A_H (MT * KCPAD)
#define B_H (NT * KCPAD)
#define STG_H (A_H + B_H)
#define NSTAGE 3
#define NCHUNK 7
#define SM_TOTAL (NSTAGE * STG_H * 2)   // 76,032 bytes

__device__ __forceinline__ void mma16816(float* c, const uint32_t* a, const uint32_t* b) {
    asm volatile(
        "mma.sync.aligned.m16n8k16.row.col.f32.bf16.bf16.f32 "
        "{%0,%1,%2,%3}, {%4,%5,%6,%7}, {%8,%9}, {%0,%1,%2,%3};"
        : "+f"(c[0]), "+f"(c[1]), "+f"(c[2]), "+f"(c[3])
        : "r"(a[0]), "r"(a[1]), "r"(a[2]), "r"(a[3]), "r"(b[0]), "r"(b[1]));
}

__global__ void __launch_bounds__(256, 3) kGemmW(int B) {
    extern __shared__ __nv_bfloat16 sm[];
    int tid = threadIdx.x, wid = tid >> 5, lane = tid & 31;
    int b0 = blockIdx.x * MT, n0 = blockIdx.y * NT;
    uint32_t sbase = smem_u32(sm);

    auto issue = [&](int c) {
        int s = c % NSTAGE;
        uint32_t abase = sbase + (uint32_t)(s * STG_H) * 2;
        uint32_t bbase = abase + A_H * 2;
        const char* ga = (const char*)g_Xb + (size_t)b0 * (KP * 2) + c * (KC * 2);
        #pragma unroll 1
        for (int i = tid; i < MT * 8; i += 256) {
            int row = i >> 3, cc = i & 7;
            uint32_t dst = abase + (uint32_t)(row * KCPAD + cc * 8) * 2;
            const char* src = ga + (size_t)row * (KP * 2) + cc * 16;
            asm volatile("cp.async.ca.shared.global [%0], [%1], 16;" :: "r"(dst), "l"(src));
        }
        const char* gb = (const char*)g_Ct + (size_t)n0 * (KP * 2) + c * (KC * 2);
        #pragma unroll 1
        for (int i = tid; i < NT * 8; i += 256) {
            int row = i >> 3, cc = i & 7;
            uint32_t dst = bbase + (uint32_t)(row * KCPAD + cc * 8) * 2;
            const char* src = gb + (size_t)row * (KP * 2) + cc * 16;
            asm volatile("cp.async.ca.shared.global [%0], [%1], 16;" :: "r"(dst), "l"(src));
        }
        asm volatile("cp.async.commit_group;");
    };

    int wm = (wid & 3) * 16;
    int wn = (wid >> 2) * 56;
    int qr = lane >> 2, qc = lane & 3;

    float acc[7][4];
    #pragma unroll
    for (int tn = 0; tn < 7; ++tn)
        #pragma unroll
        for (int e = 0; e < 4; ++e) acc[tn][e] = 0.f;

    issue(0); issue(1);

    for (int c = 0; c < NCHUNK; ++c) {
        if (c < NCHUNK - 1) { asm volatile("cp.async.wait_group 1;"); }
        else { asm volatile("cp.async.wait_group 0;"); }
        __syncthreads();
        if (c + 2 < NCHUNK) issue(c + 2);

        const __nv_bfloat16* As = sm + (c % NSTAGE) * STG_H;
        const __nv_bfloat16* Bs = As + A_H;
        #pragma unroll
        for (int k0 = 0; k0 < KC; k0 += 16) {
            uint32_t bf[7][2];
            #pragma unroll
            for (int tn = 0; tn < 7; ++tn) {
                uint2 bv = *(const uint2*)(Bs + (wn + tn * 8 + qr) * KCPAD + k0 + 4 * qc);
                bf[tn][0] = bv.x; bf[tn][1] = bv.y;
            }
            uint32_t af[4];
            {
                uint2 av0 = *(const uint2*)(As + (wm + qr) * KCPAD + k0 + 4 * qc);
                uint2 av1 = *(const uint2*)(As + (wm + qr + 8) * KCPAD + k0 + 4 * qc);
                af[0] = av0.x; af[2] = av0.y;
                af[1] = av1.x; af[3] = av1.y;
            }
            #pragma unroll
            for (int tn = 0; tn < 7; ++tn)
                mma16816(acc[tn], af, bf[tn]);
        }
    }

    __syncthreads();
    int row = b0 + wm + qr;
    #pragma unroll
    for (int tn = 0; tn < 7; ++tn) {
        int col = n0 + wn + tn * 8 + qc * 2;
        if (row < B)
            *(float2*)&g_M[(size_t)row * NCOL + col] = make_float2(acc[tn][0], acc[tn][1]);
        if (row + 8 < B)
            *(float2*)&g_M[(size_t)(row + 8) * NCOL + col] = make_float2(acc[tn][2], acc[tn][3]);
    }
}

// ============================================================
// kOut (measured-good): one warp per item, float4 staging.
// ============================================================
__global__ void kOut(const float* __restrict__ Wt, float* __restrict__ out, int B) {
    __shared__ float Ssm[256];
    __shared__ float Ms[8][784];
    __shared__ float As[8][192];
    int tid = threadIdx.x, warp = tid >> 5, lane = tid & 31;
    Ssm[tid] = g_S[tid];
    __syncthreads();
    int b = blockIdx.x * 8 + warp;
    if (b >= B) return;
    {
        const float4* mp = (const float4*)(g_M + (size_t)b * 784);
        float4* md = (float4*)Ms[warp];
        for (int i = lane; i < 196; i += 32) md[i] = mp[i];
        const float4* ap = (const float4*)(g_A + (size_t)b * 192);
        float4* ad = (float4*)As[warp];
        for (int i = lane; i < 48; i += 32) ad[i] = ap[i];
    }
    __syncwarp();
    if (lane < 21) {
        float a0 = 0.f, a1 = 0.f, a2 = 0.f;
        if (lane < 16) {
            int k = lane;
            #pragma unroll
            for (int j = 0; j < 16; ++j) {
                const float* Aj = &As[warp][j * 12];
                float s = Ssm[k * 16 + j];
                int base = (k * 16 + j) * 3;
                float m0 = Ms[warp][base], m1 = Ms[warp][base + 1], m2 = Ms[warp][base + 2];
                a0 += Aj[0] * m0 + Aj[1] * m1 + Aj[2] * m2 + Aj[9]  * s;
                a1 += Aj[3] * m0 + Aj[4] * m1 + Aj[5] * m2 + Aj[10] * s;
                a2 += Aj[6] * m0 + Aj[7] * m1 + Aj[8] * m2 + Aj[11] * s;
            }
        } else {
            int f = lane - 16;
            float v0 = Ms[warp][768 + f * 3], v1 = Ms[warp][768 + f * 3 + 1], v2 = Ms[warp][768 + f * 3 + 2];
            const float* wr = Wt + c_fidx[f] * 16;
            #pragma unroll
            for (int j = 0; j < 16; ++j) {
                const float* Aj = &As[warp][j * 12];
                float w = wr[j];
                a0 += w * (Aj[0] * v0 + Aj[1] * v1 + Aj[2] * v2 + Aj[9]);
                a1 += w * (Aj[3] * v0 + Aj[4] * v1 + Aj[5] * v2 + Aj[10]);
                a2 += w * (Aj[6] * v0 + Aj[7] * v1 + Aj[8] * v2 + Aj[11]);
            }
        }
        float* op = out + b * 63 + lane * 3;
        op[0] = a0; op[1] = a1; op[2] = a2;
    }
}

// ============================================================
extern "C" void kernel_launch(void* const* d_in, const int* in_sizes, int n_in,
                              void* d_out, int out_size) {
    const float* beta  = (const float*)d_in[0];
    const float* theta = (const float*)d_in[1];
    const float* vt    = (const float*)d_in[2];
    const float* sd    = (const float*)d_in[3];
    const float* pd    = (const float*)d_in[4];
    const float* Jreg  = (const float*)d_in[5];
    const float* W     = (const float*)d_in[6];
    const float* hm    = (const float*)d_in[7];
    const float* hc    = (const float*)d_in[8];
    int B = in_sizes[0] / 10;
    if (B > BMAX) B = BMAX;

    cudaFuncSetAttribute(kGemmW, cudaFuncAttributeMaxDynamicSharedMemorySize, SM_TOTAL);

    int nB = (B + 7) / 8;
    kC<<<dim3(NC, NCHP), 256>>>(vt, sd, pd, Jreg, W);
    kCtBatch<<<nB + 448, 256>>>(beta, theta, hm, hc, B, nB);
    kGemmW<<<dim3((B + MT - 1) / MT, NCOL / NT), 256, SM_TOTAL>>>(B);
    kOut<<<(B + 7) / 8, 256>>>(W, (float*)d_out, B);
}

// round 17
// speedup vs baseline: 1.2122x; 1.0247x over previous
#include <cuda_runtime.h>
#include <cuda_bf16.h>
#include <cstdint>
#include <math.h>

#define NVV 778
#define NC   146      // 1 + 10 beta + 135 pose_feature
#define NCOL 784      // 768 joint cols + 15 finger cols + 1 pad
#define BMAX 4096
#define KP   448      // split-K: [Xh(146)|Xh(146)|Xl(146)|pad10]
#define NCHP 7        // vertex chunks for kC

// ---- scratch (static device globals; no allocation) ----
__device__ float g_S[256];
__device__ float g_A[BMAX * 192];   // skinning transforms 16 x (R9 + t3)
__device__ float g_M[BMAX * NCOL];  // GEMM result (fp32)
__device__ __nv_bfloat16 g_Xb[BMAX * KP];   // split-bf16 X (k-permuted)
__device__ __nv_bfloat16 g_Ct[NCOL * KP];   // split-bf16 C^T (k-permuted)
__device__ float g_Cpart[NCHP][NC * NCOL];  // per-chunk partial C rows
__device__ float g_Spart[NCHP][256];
__device__ float g_JTpart[NCHP][11 * 48];

__constant__ int c_fidx[5]   = {734,333,443,555,678};
// ancestor-at-depth-s for each joint (identity-pad = -1)
__constant__ int c_anc1[16] = { -1, 1, 1, 1, 4, 4, 4, 7, 7, 7,10,10,10,13,13,13};
__constant__ int c_anc2[16] = { -1,-1, 2, 2,-1, 5, 5,-1, 8, 8,-1,11,11,-1,14,14};
__constant__ int c_anc3[16] = { -1,-1,-1, 3,-1,-1, 6,-1,-1, 9,-1,-1,12,-1,-1,15};

__device__ __forceinline__ uint32_t smem_u32(const void* p) {
    uint32_t a;
    asm("{ .reg .u64 t; cvta.to.shared.u64 t, %1; cvt.u32.u64 %0, t; }" : "=r"(a) : "l"(p));
    return a;
}

__device__ __forceinline__ void bf16_split(float v, __nv_bfloat16& hi, __nv_bfloat16& lo) {
    hi = __float2bfloat16(v);
    lo = __float2bfloat16(v - __bfloat162float(hi));
}

// k-permutation within each 16-block: pairs [p0,p4,p1,p5,p2,p6,p3,p7]
__device__ __forceinline__ int permk(int k) {
    int blk = k & ~15, kk = k & 15;
    int q = kk >> 1, r = kk & 1;
    int slot = (q < 4) ? (q << 1) : (((q - 4) << 1) + 1);
    return blk + (slot << 1) + r;
}

// ============================================================
// kC (chunked): grid (146, 7) — known-good since R11.
// ============================================================
#define CHV 112
__global__ void __launch_bounds__(256) kC(
        const float* __restrict__ vt, const float* __restrict__ sd,
        const float* __restrict__ pd, const float* __restrict__ Jreg,
        const float* __restrict__ Wt) {
    __shared__ float Ds[CHV * 3];
    __shared__ float Jr[CHV * 16];
    __shared__ float Wc[CHV * 16];
    int r = blockIdx.x, ch = blockIdx.y, t = threadIdx.x;
    int v0 = ch * CHV;
    int n = NVV - v0; if (n > CHV) n = CHV;
    const float* src = (r == 0) ? vt : (r < 11 ? sd + (r - 1) * (NVV * 3)
                                               : pd + (r - 11) * (NVV * 3));
    for (int i = t; i < n * 3; i += 256) Ds[i] = src[v0 * 3 + i];
    for (int i = t; i < n * 16; i += 256) {
        Jr[i] = Jreg[v0 * 16 + i];
        Wc[i] = Wt[v0 * 16 + i];
    }
    __syncthreads();

    int k = t >> 4, j = t & 15;
    float a0 = 0.f, a1 = 0.f, a2 = 0.f, ss = 0.f;
    #pragma unroll 4
    for (int v = 0; v < n; ++v) {
        float e = Jr[v * 16 + k] * Wc[v * 16 + j];
        ss += e;
        a0 += e * Ds[v * 3 + 0];
        a1 += e * Ds[v * 3 + 1];
        a2 += e * Ds[v * 3 + 2];
    }
    float* out = g_Cpart[ch] + (size_t)r * NCOL;
    out[t * 3 + 0] = a0;
    out[t * 3 + 1] = a1;
    out[t * 3 + 2] = a2;
    if (t < 15) {
        int fv = c_fidx[t / 3];
        float fvv = 0.f;
        if (fv >= v0 && fv < v0 + n) fvv = Ds[(fv - v0) * 3 + (t % 3)];
        out[768 + t] = fvv;
    }
    if (t == 15) out[783] = 0.f;
    if (r == 0) g_Spart[ch][t] = ss;
    if (r < 11 && t < 48) {
        int jj = t / 3, cc = t - jj * 3;
        float jt = 0.f;
        #pragma unroll 4
        for (int v = 0; v < n; ++v) jt += Jr[v * 16 + jj] * Ds[v * 3 + cc];
        g_JTpart[ch][r * 48 + t] = jt;
    }
}

// ============================================================
// kCtBatch: one launch.  Batch blocks FIRST (long pole), then
// 448 C-reduce blocks.  (R16 measured-good)
// ============================================================
__global__ void __launch_bounds__(256) kCtBatch(
        const float* __restrict__ beta, const float* __restrict__ theta,
        const float* __restrict__ hm, const float* __restrict__ hc, int B, int nB) {
    int tid = threadIdx.x;
    if ((int)blockIdx.x >= nB) {
        int idx = (blockIdx.x - nB) * 256 + tid;
        if (idx >= NC * NCOL) return;
        int r = idx / NCOL, nn = idx - r * NCOL;
        float s = 0.f;
        #pragma unroll
        for (int ch = 0; ch < NCHP; ++ch) s += g_Cpart[ch][(size_t)r * NCOL + nn];
        __nv_bfloat16 hi, lo;
        bf16_split(s, hi, lo);
        __nv_bfloat16* row = g_Ct + (size_t)nn * KP;
        row[permk(r)] = hi;
        row[permk(146 + r)] = lo;
        row[permk(292 + r)] = hi;
        if (r == 0) {
            __nv_bfloat16 z = __float2bfloat16(0.f);
            #pragma unroll
            for (int l = 438; l < KP; ++l) row[permk(l)] = z;
        }
        return;
    }

    // ---- batch part ----
    __shared__ float hcs[45 * 45];
    __shared__ float hms[45];
    __shared__ float JTs[11 * 48];
    __shared__ float wsPose[8][48];
    __shared__ float wsJ[8][48];
    __shared__ float wsBeta[8][10];
    __shared__ float wsX[8][146];

    int warp = tid >> 5, lane = tid & 31;
    for (int i = tid; i < 2025; i += 256) hcs[i] = hc[i];
    if (tid < 45) hms[tid] = hm[tid];
    for (int i = tid; i < 528; i += 256) {
        float s = 0.f;
        #pragma unroll
        for (int ch = 0; ch < NCHP; ++ch) s += g_JTpart[ch][i];
        JTs[i] = s;
    }
    int bb = blockIdx.x;
    if (bb == 0) {
        float s = 0.f;
        #pragma unroll
        for (int ch = 0; ch < NCHP; ++ch) s += g_Spart[ch][tid];
        g_S[tid] = s;
    }
    __syncthreads();

    int b = bb * 8 + warp;
    if (b >= B) return;

    float* P = wsPose[warp];
    const float* th = theta + b * 48;
    if (lane < 16) { P[lane] = th[lane]; P[lane + 16] = th[lane + 16]; P[lane + 32] = th[lane + 32]; }
    if (lane < 10) wsBeta[warp][lane] = beta[b * 10 + lane];
    __syncwarp();

    int i0 = lane, i1 = lane + 32;
    float acc0 = hms[i0];
    float acc1 = (i1 < 45) ? hms[i1] : 0.f;
    #pragma unroll 5
    for (int p = 0; p < 45; ++p) {
        float tv = P[3 + p];
        acc0 += tv * hcs[p * 45 + i0];
        if (i1 < 45) acc1 += tv * hcs[p * 45 + i1];
    }
    __syncwarp();
    P[3 + i0] = acc0;
    if (i1 < 45) P[3 + i1] = acc1;
    __syncwarp();

    float* xs = wsX[warp];
    float R[9] = {1.f, 0.f, 0.f, 0.f, 1.f, 0.f, 0.f, 0.f, 1.f};
    float tl0 = 0.f, tl1 = 0.f, tl2 = 0.f;
    if (lane < 16) {
        float rx = P[3 * lane], ry = P[3 * lane + 1], rz = P[3 * lane + 2];
        float ex = rx + 1e-8f, ey = ry + 1e-8f, ez = rz + 1e-8f;
        float ang = sqrtf(ex * ex + ey * ey + ez * ez);
        float inv = 1.0f / ang;
        float ax = rx * inv, ay = ry * inv, az = rz * inv;
        float s, co;
        __sincosf(ang, &s, &co);
        float t1 = 1.0f - co;
        R[0] = 1.0f - t1 * (ay * ay + az * az);
        R[1] = -s * az + t1 * ax * ay;
        R[2] =  s * ay + t1 * ax * az;
        R[3] =  s * az + t1 * ax * ay;
        R[4] = 1.0f - t1 * (ax * ax + az * az);
        R[5] = -s * ax + t1 * ay * az;
        R[6] = -s * ay + t1 * ax * az;
        R[7] =  s * ax + t1 * ay * az;
        R[8] = 1.0f - t1 * (ax * ax + ay * ay);
        if (lane >= 1) {
            #pragma unroll
            for (int e = 0; e < 9; ++e)
                xs[11 + (lane - 1) * 9 + e] = R[e] - ((e == 0 || e == 4 || e == 8) ? 1.0f : 0.0f);
        }
    }
    if (lane == 0) xs[0] = 1.0f;
    if (lane < 10) xs[1 + lane] = wsBeta[warp][lane];
    __syncwarp();

    {
        __nv_bfloat16* xb = g_Xb + (size_t)b * KP;
        for (int l = lane; l < KP; l += 32) {
            __nv_bfloat16 o;
            if (l < 146) o = __float2bfloat16(xs[l]);
            else if (l < 292) o = __float2bfloat16(xs[l - 146]);
            else if (l < 438) {
                float v = xs[l - 292];
                __nv_bfloat16 h = __float2bfloat16(v);
                o = __float2bfloat16(v - __bfloat162float(h));
            } else o = __float2bfloat16(0.f);
            xb[permk(l)] = o;
        }
    }

    float* Jv = wsJ[warp];
    for (int o = lane; o < 48; o += 32) {
        float acc = JTs[o];
        #pragma unroll
        for (int s2 = 0; s2 < 10; ++s2) acc += wsBeta[warp][s2] * JTs[(s2 + 1) * 48 + o];
        Jv[o] = acc;
    }
    __syncwarp();

    {
        int li = (lane < 16) ? lane : 0;
        if (li == 0) { tl0 = Jv[0]; tl1 = Jv[1]; tl2 = Jv[2]; }
        else {
            int p = (li == 1 || li == 4 || li == 7 || li == 10 || li == 13) ? 0 : li - 1;
            tl0 = Jv[3 * li + 0] - Jv[3 * p + 0];
            tl1 = Jv[3 * li + 1] - Jv[3 * p + 1];
            tl2 = Jv[3 * li + 2] - Jv[3 * p + 2];
        }
    }

    int li = (lane < 16) ? lane : 0;
    float M[9], Tt[3];
    #pragma unroll
    for (int e = 0; e < 9; ++e) M[e] = __shfl_sync(0xFFFFFFFF, R[e], 0);
    Tt[0] = __shfl_sync(0xFFFFFFFF, tl0, 0);
    Tt[1] = __shfl_sync(0xFFFFFFFF, tl1, 0);
    Tt[2] = __shfl_sync(0xFFFFFFFF, tl2, 0);
    const int* ancs[3] = {c_anc1, c_anc2, c_anc3};
    #pragma unroll
    for (int s = 0; s < 3; ++s) {
        int vs = ancs[s][li];
        int srcl = (vs >= 0) ? vs : 0;
        float Rs[9], ts0, ts1, ts2;
        #pragma unroll
        for (int e = 0; e < 9; ++e) Rs[e] = __shfl_sync(0xFFFFFFFF, R[e], srcl);
        ts0 = __shfl_sync(0xFFFFFFFF, tl0, srcl);
        ts1 = __shfl_sync(0xFFFFFFFF, tl1, srcl);
        ts2 = __shfl_sync(0xFFFFFFFF, tl2, srcl);
        if (vs >= 0) {
            float n0 = M[0] * ts0 + M[1] * ts1 + M[2] * ts2 + Tt[0];
            float n1 = M[3] * ts0 + M[4] * ts1 + M[5] * ts2 + Tt[1];
            float n2 = M[6] * ts0 + M[7] * ts1 + M[8] * ts2 + Tt[2];
            Tt[0] = n0; Tt[1] = n1; Tt[2] = n2;
            float NM[9];
            #pragma unroll
            for (int rr = 0; rr < 3; ++rr)
                #pragma unroll
                for (int cc = 0; cc < 3; ++cc)
                    NM[rr * 3 + cc] = M[rr * 3 + 0] * Rs[0 + cc] +
                                      M[rr * 3 + 1] * Rs[3 + cc] +
                                      M[rr * 3 + 2] * Rs[6 + cc];
            #pragma unroll
            for (int e = 0; e < 9; ++e) M[e] = NM[e];
        }
    }

    if (lane < 16) {
        float jx = Jv[3 * lane], jy = Jv[3 * lane + 1], jz = Jv[3 * lane + 2];
        Tt[0] -= M[0] * jx + M[1] * jy + M[2] * jz;
        Tt[1] -= M[3] * jx + M[4] * jy + M[5] * jz;
        Tt[2] -= M[6] * jx + M[7] * jy + M[8] * jz;
        float* ap = g_A + b * 192 + lane * 12;
        #pragma unroll
        for (int e = 0; e < 9; ++e) ap[e] = M[e];
        ap[9] = Tt[0]; ap[10] = Tt[1]; ap[11] = Tt[2];
    }
}

// ============================================================
// kGemmW: pipelined mma.sync bf16 GEMM (R14/R16 measured-good).
// ============================================================
#define MT 64
#define NT 112
#define KC 64
#define KCPAD 72
#define A_H (MT * KCPAD)
#define B_H (NT * KCPAD)
#define STG_H (A_H + B_H)
#define NSTAGE 3
#define NCHUNK 7
#define SM_TOTAL (NSTAGE * STG_H * 2)   // 76,032 bytes

__device__ __forceinline__ void mma16816(float* c, const uint32_t* a, const uint32_t* b) {
    asm volatile(
        "mma.sync.aligned.m16n8k16.row.col.f32.bf16.bf16.f32 "
        "{%0,%1,%2,%3}, {%4,%5,%6,%7}, {%8,%9}, {%0,%1,%2,%3};"
        : "+f"(c[0]), "+f"(c[1]), "+f"(c[2]), "+f"(c[3])
        : "r"(a[0]), "r"(a[1]), "r"(a[2]), "r"(a[3]), "r"(b[0]), "r"(b[1]));
}

__global__ void __launch_bounds__(256, 3) kGemmW(int B) {
    extern __shared__ __nv_bfloat16 sm[];
    int tid = threadIdx.x, wid = tid >> 5, lane = tid & 31;
    int b0 = blockIdx.x * MT, n0 = blockIdx.y * NT;
    uint32_t sbase = smem_u32(sm);

    auto issue = [&](int c) {
        int s = c % NSTAGE;
        uint32_t abase = sbase + (uint32_t)(s * STG_H) * 2;
        uint32_t bbase = abase + A_H * 2;
        const char* ga = (const char*)g_Xb + (size_t)b0 * (KP * 2) + c * (KC * 2);
        #pragma unroll 1
        for (int i = tid; i < MT * 8; i += 256) {
            int row = i >> 3, cc = i & 7;
            uint32_t dst = abase + (uint32_t)(row * KCPAD + cc * 8) * 2;
            const char* src = ga + (size_t)row * (KP * 2) + cc * 16;
            asm volatile("cp.async.ca.shared.global [%0], [%1], 16;" :: "r"(dst), "l"(src));
        }
        const char* gb = (const char*)g_Ct + (size_t)n0 * (KP * 2) + c * (KC * 2);
        #pragma unroll 1
        for (int i = tid; i < NT * 8; i += 256) {
            int row = i >> 3, cc = i & 7;
            uint32_t dst = bbase + (uint32_t)(row * KCPAD + cc * 8) * 2;
            const char* src = gb + (size_t)row * (KP * 2) + cc * 16;
            asm volatile("cp.async.ca.shared.global [%0], [%1], 16;" :: "r"(dst), "l"(src));
        }
        asm volatile("cp.async.commit_group;");
    };

    int wm = (wid & 3) * 16;
    int wn = (wid >> 2) * 56;
    int qr = lane >> 2, qc = lane & 3;

    float acc[7][4];
    #pragma unroll
    for (int tn = 0; tn < 7; ++tn)
        #pragma unroll
        for (int e = 0; e < 4; ++e) acc[tn][e] = 0.f;

    issue(0); issue(1);

    for (int c = 0; c < NCHUNK; ++c) {
        if (c < NCHUNK - 1) { asm volatile("cp.async.wait_group 1;"); }
        else { asm volatile("cp.async.wait_group 0;"); }
        __syncthreads();
        if (c + 2 < NCHUNK) issue(c + 2);

        const __nv_bfloat16* As = sm + (c % NSTAGE) * STG_H;
        const __nv_bfloat16* Bs = As + A_H;
        #pragma unroll
        for (int k0 = 0; k0 < KC; k0 += 16) {
            uint32_t bf[7][2];
            #pragma unroll
            for (int tn = 0; tn < 7; ++tn) {
                uint2 bv = *(const uint2*)(Bs + (wn + tn * 8 + qr) * KCPAD + k0 + 4 * qc);
                bf[tn][0] = bv.x; bf[tn][1] = bv.y;
            }
            uint32_t af[4];
            {
                uint2 av0 = *(const uint2*)(As + (wm + qr) * KCPAD + k0 + 4 * qc);
                uint2 av1 = *(const uint2*)(As + (wm + qr + 8) * KCPAD + k0 + 4 * qc);
                af[0] = av0.x; af[2] = av0.y;
                af[1] = av1.x; af[3] = av1.y;
            }
            #pragma unroll
            for (int tn = 0; tn < 7; ++tn)
                mma16816(acc[tn], af, bf[tn]);
        }
    }

    __syncthreads();
    int row = b0 + wm + qr;
    #pragma unroll
    for (int tn = 0; tn < 7; ++tn) {
        int col = n0 + wn + tn * 8 + qc * 2;
        if (row < B)
            *(float2*)&g_M[(size_t)row * NCOL + col] = make_float2(acc[tn][0], acc[tn][1]);
        if (row + 8 < B)
            *(float2*)&g_M[(size_t)(row + 8) * NCOL + col] = make_float2(acc[tn][2], acc[tn][3]);
    }
}

// ============================================================
// kOut: one warp per item; block-cooperative cp.async staging
// (no LDG->STS register chains; single commit/wait).
// ============================================================
__global__ void __launch_bounds__(256) kOut(const float* __restrict__ Wt,
                                            float* __restrict__ out, int B) {
    __shared__ float Ssm[256];
    __shared__ float Ms[8][784];   // row stride 3136B (16B-aligned)
    __shared__ float As[8][192];
    int tid = threadIdx.x, warp = tid >> 5, lane = tid & 31;
    Ssm[tid] = g_S[tid];

    int b0 = blockIdx.x * 8;
    int nIt = B - b0; if (nIt > 8) nIt = 8;
    {
        uint32_t mBase = smem_u32(&Ms[0][0]);
        const char* msrc = (const char*)(g_M + (size_t)b0 * 784);
        int totM = nIt * 196;                      // 16B chunks
        for (int i = tid; i < totM; i += 256) {
            uint32_t dst = mBase + (uint32_t)i * 16;   // Ms rows contiguous
            asm volatile("cp.async.ca.shared.global [%0], [%1], 16;"
                         :: "r"(dst), "l"(msrc + (size_t)i * 16));
        }
        uint32_t aBase = smem_u32(&As[0][0]);
        const char* asrc = (const char*)(g_A + (size_t)b0 * 192);
        int totA = nIt * 48;
        for (int i = tid; i < totA; i += 256) {
            uint32_t dst = aBase + (uint32_t)i * 16;
            asm volatile("cp.async.ca.shared.global [%0], [%1], 16;"
                         :: "r"(dst), "l"(asrc + (size_t)i * 16));
        }
        asm volatile("cp.async.commit_group;");
        asm volatile("cp.async.wait_group 0;");
    }
    __syncthreads();

    int b = b0 + warp;
    if (b >= B) return;
    if (lane < 21) {
        float a0 = 0.f, a1 = 0.f, a2 = 0.f;
        if (lane < 16) {
            int k = lane;
            #pragma unroll
            for (int j = 0; j < 16; ++j) {
                const float* Aj = &As[warp][j * 12];
                float s = Ssm[k * 16 + j];
                int base = (k * 16 + j) * 3;
                float m0 = Ms[warp][base], m1 = Ms[warp][base + 1], m2 = Ms[warp][base + 2];
                a0 += Aj[0] * m0 + Aj[1] * m1 + Aj[2] * m2 + Aj[9]  * s;
                a1 += Aj[3] * m0 + Aj[4] * m1 + Aj[5] * m2 + Aj[10] * s;
                a2 += Aj[6] * m0 + Aj[7] * m1 + Aj[8] * m2 + Aj[11] * s;
            }
        } else {
            int f = lane - 16;
            float v0 = Ms[warp][768 + f * 3], v1 = Ms[warp][768 + f * 3 + 1], v2 = Ms[warp][768 + f * 3 + 2];
            const float* wr = Wt + c_fidx[f] * 16;
            #pragma unroll
            for (int j = 0; j < 16; ++j) {
                const float* Aj = &As[warp][j * 12];
                float w = wr[j];
                a0 += w * (Aj[0] * v0 + Aj[1] * v1 + Aj[2] * v2 + Aj[9]);
                a1 += w * (Aj[3] * v0 + Aj[4] * v1 + Aj[5] * v2 + Aj[10]);
                a2 += w * (Aj[6] * v0 + Aj[7] * v1 + Aj[8] * v2 + Aj[11]);
            }
        }
        float* op = out + b * 63 + lane * 3;
        op[0] = a0; op[1] = a1; op[2] = a2;
    }
}

// ============================================================
extern "C" void kernel_launch(void* const* d_in, const int* in_sizes, int n_in,
                              void* d_out, int out_size) {
    const float* beta  = (const float*)d_in[0];
    const float* theta = (const float*)d_in[1];
    const float* vt    = (const float*)d_in[2];
    const float* sd    = (const float*)d_in[3];
    const float* pd    = (const float*)d_in[4];
    const float* Jreg  = (const float*)d_in[5];
    const float* W     = (const float*)d_in[6];
    const float* hm    = (const float*)d_in[7];
    const float* hc    = (const float*)d_in[8];
    int B = in_sizes[0] / 10;
    if (B > BMAX) B = BMAX;

    cudaFuncSetAttribute(kGemmW, cudaFuncAttributeMaxDynamicSharedMemorySize, SM_TOTAL);

    int nB = (B + 7) / 8;
    kC<<<dim3(NC, NCHP), 256>>>(vt, sd, pd, Jreg, W);
    kCtBatch<<<nB + 448, 256>>>(beta, theta, hm, hc, B, nB);
    kGemmW<<<dim3((B + MT - 1) / MT, NCOL / NT), 256, SM_TOTAL>>>(B);
    kOut<<<(B + 7) / 8, 256>>>(W, (float*)d_out, B);
}